// round 15
// baseline (speedup 1.0000x reference)
#include <cuda_runtime.h>
#include <cuda_fp16.h>

#define HID 128
#define INP 320
#define CH  448
#define BATCH 8
#define IH 64
#define IW 128
#define HW (IH * IW)

#define KCM 64     // K per chunk
#define NKC 7      // 448/64
#define KSUB 16    // dw sub-chunk channels

typedef unsigned int u32;

// ---------------- device scratch ----------------
__device__ float g_qwd[3][CH * 9];                        // dequantized dw weights
__device__ __align__(16) __half g_wpA[3][NKC][128 * KCM]; // pw weights as exact ints in fp16
__device__ float g_Z [BATCH * HID * IH * IW];
__device__ float g_RH[BATCH * HID * IH * IW];
__device__ float g_amaxf[6];

// ---------------- PTX helpers (base sm_103-safe) ----------------
__device__ __forceinline__ u32 smem_u32(const void* p) {
    u32 a;
    asm("{ .reg .u64 t; cvta.to.shared.u64 t, %1; cvt.u32.u64 %0, t; }" : "=r"(a) : "l"(p));
    return a;
}
__device__ __forceinline__ void ldm4(u32& r0, u32& r1, u32& r2, u32& r3, u32 addr) {
    asm volatile("ldmatrix.sync.aligned.m8n8.x4.shared.b16 {%0,%1,%2,%3}, [%4];"
                 : "=r"(r0), "=r"(r1), "=r"(r2), "=r"(r3) : "r"(addr));
}
__device__ __forceinline__ void mma16816(float* d, const u32* a, u32 b0, u32 b1) {
    asm volatile("mma.sync.aligned.m16n8k16.row.col.f32.f16.f16.f32 "
                 "{%0,%1,%2,%3},{%4,%5,%6,%7},{%8,%9},{%0,%1,%2,%3};"
                 : "+f"(d[0]), "+f"(d[1]), "+f"(d[2]), "+f"(d[3])
                 : "r"(a[0]), "r"(a[1]), "r"(a[2]), "r"(a[3]), "r"(b0), "r"(b1));
}
__device__ __forceinline__ void cpa4(u32 dst, const void* src, bool v) {
    asm volatile("cp.async.ca.shared.global [%0], [%1], 4, %2;"
                 :: "r"(dst), "l"(src), "r"(v ? 4u : 0u) : "memory");
}
__device__ __forceinline__ void cpa16(u32 dst, const void* src, bool v) {
    asm volatile("cp.async.cg.shared.global [%0], [%1], 16, %2;"
                 :: "r"(dst), "l"(src), "r"(v ? 16u : 0u) : "memory");
}
#define CP_COMMIT() asm volatile("cp.async.commit_group;" ::: "memory")
#define CP_WAIT1()  asm volatile("cp.async.wait_group 1;" ::: "memory")

// ---------------- prep kernels ----------------
__global__ void amax_all_kernel(const float* wdz, const float* wdr, const float* wdq,
                                const float* wpz, const float* wpr, const float* wpq) {
    __shared__ float red[256];
    const float* ws[6] = {wdz, wdr, wdq, wpz, wpr, wpq};
    const int n = blockIdx.x < 3 ? CH * 9 : HID * CH;
    const float* w = ws[blockIdx.x];
    float m = 0.f;
    for (int i = threadIdx.x; i < n; i += 256) m = fmaxf(m, fabsf(w[i]));
    red[threadIdx.x] = m; __syncthreads();
    for (int s = 128; s > 0; s >>= 1) {
        if (threadIdx.x < s) red[threadIdx.x] = fmaxf(red[threadIdx.x], red[threadIdx.x + s]);
        __syncthreads();
    }
    if (threadIdx.x == 0) g_amaxf[blockIdx.x] = red[0];
}
__global__ void quant_dw_kernel(const float* w0, const float* w1, const float* w2) {
    const int g = blockIdx.y;
    const float* w = g == 0 ? w0 : (g == 1 ? w1 : w2);
    const float scale = fmaxf(g_amaxf[g], 1e-8f) / 127.f;
    int i = blockIdx.x * 256 + threadIdx.x;
    if (i < CH * 9) {
        float q = rintf(w[i] / scale);
        q = fminf(fmaxf(q, -128.f), 127.f);
        g_qwd[g][i] = q * scale;
    }
}
__global__ void quant_pw_kernel(const float* w0, const float* w1, const float* w2) {
    const int g = blockIdx.y;
    const float* w = g == 0 ? w0 : (g == 1 ? w1 : w2);
    const float scale = fmaxf(g_amaxf[3 + g], 1e-8f) / 127.f;
    int i = blockIdx.x * 256 + threadIdx.x;
    if (i < HID * CH) {
        float q = rintf(w[i] / scale);
        q = fminf(fmaxf(q, -128.f), 127.f);
        int o = i / CH, k = i - o * CH;
        g_wpA[g][k >> 6][o * 64 + (k & 63)] = __float2half_rn(q);   // exact integer in fp16
    }
}

// ---------------- fused mainloop: dw and MMA software-pipelined ----------------
// B double-buffered by chunk parity; chunk c's MMA runs as 1 k-slice per sub-stage
// of chunk c+1 (interleaved with dw in the same inter-barrier region).
// A-issue at (t&3)==2 so cp.async writes to A parity p start only AFTER the last
// MMA read of parity p (race fixed vs R14).
template<int NG>
__device__ __forceinline__ void mainloop(
    char* sm, u32 sbase,
    const float* __restrict__ src0, const float* __restrict__ srcx,
    const float* __restrict__ bdA, const float* __restrict__ bdB,
    int gate0, int b, int y0, int x0, float acc[2][8][4])
{
    constexpr int NT     = 512;
    constexpr int IN_SZ  = 17152;
    constexpr int OFF_WD = 3 * IN_SZ;
    constexpr int WD_SZ  = NG * 2304;
    constexpr int OFF_BD = OFF_WD + 2 * WD_SZ;
    constexpr int BD_SZ  = NG * 256;
    constexpr int OFF_A  = OFF_BD + 2 * BD_SZ;
    constexpr int ASZ    = 18432;
    constexpr int OFF_B  = OFF_A + 2 * NG * ASZ;
    constexpr int NJT    = (NG == 2) ? 8 : 4;
    constexpr int PT     = NJT / 2;
    constexpr int XPT    = (NG == 2) ? 8 : 4;   // x per dw thread
    constexpr int NL4    = (XPT + 8) / 4;

    const int tid = threadIdx.x;
    const int wid = tid >> 5, lane = tid & 31;
    const int g   = (NG == 2) ? (wid >> 3) : 0;
    const int w   = (NG == 2) ? (wid & 7) : wid;
    const int ogB = (w & 3) * 32;
    const int pgB = (NG == 2) ? (w >> 2) * 64 : (w >> 2) * 32;

    const int g2 = (NG == 2) ? (tid >> 8) : 0;
    const int t2 = (NG == 2) ? (tid & 255) : tid;
    const int cD = t2 & 15;
    const int yD = (t2 >> 4) & 3;
    const int xgD = t2 >> 6;

    #pragma unroll
    for (int mi = 0; mi < 2; mi++)
        #pragma unroll
        for (int nj = 0; nj < 8; nj++)
            #pragma unroll
            for (int e = 0; e < 4; e++) acc[mi][nj][e] = 0.f;

    // ---- halo slot descriptors ----
    u32 hs_sm[2], hs_off[2];
    bool hs_ok[2], hs_val[2];
    #pragma unroll
    for (int k = 0; k < 2; k++) {
        int i = tid + k * NT;
        hs_ok[k] = i < 960;
        int ii = hs_ok[k] ? i : 0;
        int c = ii / 60, rem = ii - c * 60;
        int row = rem / 10, j = rem - row * 10;
        int gy = y0 - 1 + row, gx = x0 - 4 + 4 * j;
        bool valid = ((unsigned)gy < IH) && ((unsigned)gx < IW) && (gx + 3 < IW);
        hs_val[k] = valid;
        hs_off[k] = (u32)(c * HW + (valid ? gy * IW + gx : 0));
        hs_sm[k]  = (u32)(c * 1072 + row * 176 + j * 16);
    }
    const float* p0  = src0 + b * HID * HW;
    const float* pxp = srcx + b * INP * HW;

    auto issue_halo = [&](int s, int buf) {
        const u32 dstb = sbase + (u32)(buf * IN_SZ);
        const int c0 = (s >> 2) * KCM + (s & 3) * KSUB;
        const float* base = (c0 < HID) ? (p0 + c0 * HW) : (pxp + (c0 - HID) * HW);
        #pragma unroll
        for (int k = 0; k < 2; k++)
            if (hs_ok[k]) cpa16(dstb + hs_sm[k], base + hs_off[k], hs_val[k]);
    };
    auto issue_wd = [&](int cn) {
        const int wb = cn & 1;
        for (int i = tid; i < NG * 576; i += NT) {
            int gg = (NG == 2) ? (i >= 576) : 0;
            int j = i - gg * 576;
            cpa4(sbase + OFF_WD + wb * WD_SZ + gg * 2304 + j * 4,
                 &g_qwd[gate0 + gg][cn * 576 + j], true);
        }
        if (tid < NG * 64) {
            int gg = tid >> 6, j = tid & 63;
            cpa4(sbase + OFF_BD + wb * BD_SZ + gg * 256 + j * 4,
                 (gg == 0 ? bdA : bdB) + cn * 64 + j, true);
        }
    };
    auto issue_A = [&](int cn) {
        const int ab = cn & 1;
        for (int i = tid; i < NG * 1024; i += NT) {
            int gg = i >> 10, jj = i & 1023;
            int o = jj >> 3, c16 = jj & 7;
            cpa16(sbase + OFF_A + (ab * NG + gg) * ASZ + o * 144 + c16 * 16,
                  (const int4*)&g_wpA[gate0 + gg][cn][0] + jj, true);
        }
    };

    // ldmatrix per-lane offsets
    const u32 aOff = (u32)((lane & 15) * 144 + ((lane >> 4) << 4));
    const u32 bOff = (u32)(((lane & 7) + ((lane >> 4) << 3)) * 144 + (((lane >> 3) & 1) << 4));

    // one MMA k-slice of chunk kcp
    auto mma_slice = [&](int kcp, int ks) {
        const u32 aB = sbase + OFF_A + ((u32)((kcp & 1) * NG + g)) * ASZ + ogB * 144 + aOff;
        const u32 bB = sbase + OFF_B + ((u32)((kcp & 1) * NG + g)) * ASZ + pgB * 144 + bOff;
        u32 af0[4], af1[4];
        ldm4(af0[0], af0[1], af0[2], af0[3], aB + ks * 32);
        ldm4(af1[0], af1[1], af1[2], af1[3], aB + 16 * 144 + ks * 32);
        #pragma unroll
        for (int p = 0; p < PT; p++) {
            u32 r0, r1, r2, r3;
            ldm4(r0, r1, r2, r3, bB + p * 16 * 144 + ks * 32);
            mma16816(acc[0][2 * p],     af0, r0, r1);
            mma16816(acc[0][2 * p + 1], af0, r2, r3);
            mma16816(acc[1][2 * p],     af1, r0, r1);
            mma16816(acc[1][2 * p + 1], af1, r2, r3);
        }
    };

    // prologue: distance-2 prefetch (group index == target stage)
    issue_halo(0, 0); issue_wd(0); CP_COMMIT();   // target 0
    issue_halo(1, 1);              CP_COMMIT();   // target 1  (A(0) issues at stage 0 via t=2)

    int ibuf = 0;
    for (int s = 0; s < 28; s++) {
        CP_WAIT1();
        __syncthreads();
        const int t = s + 2;
        if (t < 28) {
            int tb = ibuf + 2; if (tb >= 3) tb -= 3;
            issue_halo(t, tb);
            if ((t & 3) == 0) issue_wd(t >> 2);
            if ((t & 3) == 2) issue_A(t >> 2);    // parity-safe: after last reader of that A buffer
        }
        CP_COMMIT();

        // ---- depthwise (writes B[kc&1]) ----
        const int sub = s & 3, kc = s >> 2, wb = kc & 1;
        const int kk = sub * KSUB + cD;
        const float* wds = (const float*)(sm + OFF_WD + wb * WD_SZ + g2 * 2304) + kk * 9;
        float wv[9];
        #pragma unroll
        for (int j = 0; j < 9; j++) wv[j] = wds[j];
        const float bv = ((const float*)(sm + OFF_BD + wb * BD_SZ + g2 * 256))[kk];
        const float* ipc = (const float*)(sm + ibuf * IN_SZ) + cD * 268 + yD * 44 + XPT * xgD;

        float ad[XPT];
        #pragma unroll
        for (int i = 0; i < XPT; i++) ad[i] = bv;
        #pragma unroll
        for (int r = 0; r < 3; r++) {
            float f[NL4 * 4];
            #pragma unroll
            for (int l = 0; l < NL4; l++)
                *(float4*)&f[l * 4] = *(const float4*)(ipc + r * 44 + l * 4);
            #pragma unroll
            for (int i = 0; i < XPT; i++) {
                ad[i] = fmaf(wv[r * 3 + 0], f[i + 3], ad[i]);
                ad[i] = fmaf(wv[r * 3 + 1], f[i + 4], ad[i]);
                ad[i] = fmaf(wv[r * 3 + 2], f[i + 5], ad[i]);
            }
        }
        char* bdst = sm + OFF_B + (wb * NG + g2) * ASZ + ((yD * 32 + XPT * xgD) * 144 + kk * 2);
        #pragma unroll
        for (int i = 0; i < XPT; i++)
            *(__half*)(bdst + i * 144) = __float2half_rn(ad[i]);

        // ---- interleaved MMA slice of previous chunk (reads A/B parity (kc-1)&1) ----
        if (kc >= 1) mma_slice(kc - 1, sub);

        if (++ibuf == 3) ibuf = 0;
    }
    // drain: chunk 6 MMA
    __syncthreads();
    #pragma unroll
    for (int ks = 0; ks < 4; ks++) mma_slice(NKC - 1, ks);
}

// ---------------- zr kernel ----------------
#define SMEM_ZR (3*17152 + 2*2*2304 + 2*2*256 + 2*2*18432 + 2*2*18432)   // 209152
#define SMEM_Q  (3*17152 + 2*1*2304 + 2*1*256 + 2*1*18432 + 2*1*18432)   // 130304

__global__ void __launch_bounds__(512) zr_kernel(
    const float* __restrict__ h, const float* __restrict__ x,
    const float* __restrict__ bdz, const float* __restrict__ bdr,
    const float* __restrict__ bpz, const float* __restrict__ bpr)
{
    extern __shared__ char sm[];
    const u32 sbase = smem_u32(sm);
    const int b = blockIdx.x >> 6, tt = blockIdx.x & 63;
    const int y0 = (tt >> 2) * 4, x0 = (tt & 3) * 32;

    float acc[2][8][4];
    mainloop<2>(sm, sbase, h, x, bdz, bdr, 0, b, y0, x0, acc);

    const int wid = threadIdx.x >> 5, lane = threadIdx.x & 31;
    const int g = wid >> 3, w = wid & 7;
    const int ogB = (w & 3) * 32, pgB = (w >> 2) * 64;
    const float sc = fmaxf(g_amaxf[3 + g], 1e-8f) / 127.f;
    const float* bp = g ? bpr : bpz;
    const int r4 = lane >> 2, cp = (lane & 3) * 2;

    #pragma unroll
    for (int mi = 0; mi < 2; mi++)
        #pragma unroll
        for (int hh = 0; hh < 2; hh++) {
            const int oc = ogB + mi * 16 + r4 + hh * 8;
            const float bias = bp[oc];
            #pragma unroll
            for (int nj = 0; nj < 8; nj++) {
                const int px = pgB + nj * 8 + cp;
                const int dst = ((b * HID + oc) * IH + y0 + (px >> 5)) * IW + x0 + (px & 31);
                float v0 = acc[mi][nj][hh * 2]     * sc + bias;
                float v1 = acc[mi][nj][hh * 2 + 1] * sc + bias;
                v0 = 1.f / (1.f + __expf(-v0));
                v1 = 1.f / (1.f + __expf(-v1));
                if (g == 0) {
                    *(float2*)(g_Z + dst) = make_float2(v0, v1);
                } else {
                    const float2 hv = *(const float2*)(h + dst);
                    *(float2*)(g_RH + dst) = make_float2(v0 * hv.x, v1 * hv.y);
                }
            }
        }
}

// ---------------- q kernel + final blend ----------------
__global__ void __launch_bounds__(512) q_kernel(
    const float* __restrict__ h, const float* __restrict__ x,
    const float* __restrict__ bdq, const float* __restrict__ bpq,
    float* __restrict__ out)
{
    extern __shared__ char sm[];
    const u32 sbase = smem_u32(sm);
    const int b = blockIdx.x >> 6, tt = blockIdx.x & 63;
    const int y0 = (tt >> 2) * 4, x0 = (tt & 3) * 32;

    float acc[2][8][4];
    mainloop<1>(sm, sbase, g_RH, x, bdq, bdq, 2, b, y0, x0, acc);

    const int wid = threadIdx.x >> 5, lane = threadIdx.x & 31;
    const int ogB = (wid & 3) * 32, pgB = (wid >> 2) * 32;
    const float sc = fmaxf(g_amaxf[5], 1e-8f) / 127.f;
    const int r4 = lane >> 2, cp = (lane & 3) * 2;

    #pragma unroll
    for (int mi = 0; mi < 2; mi++)
        #pragma unroll
        for (int hh = 0; hh < 2; hh++) {
            const int oc = ogB + mi * 16 + r4 + hh * 8;
            const float bias = bpq[oc];
            #pragma unroll
            for (int nj = 0; nj < 4; nj++) {
                const int px = pgB + nj * 8 + cp;
                const int dst = ((b * HID + oc) * IH + y0 + (px >> 5)) * IW + x0 + (px & 31);
                float q0 = tanhf(acc[mi][nj][hh * 2]     * sc + bias);
                float q1 = tanhf(acc[mi][nj][hh * 2 + 1] * sc + bias);
                const float2 zv = *(const float2*)(g_Z + dst);
                const float2 hv = *(const float2*)(h + dst);
                *(float2*)(out + dst) = make_float2(
                    (1.f - zv.x) * hv.x + zv.x * q0,
                    (1.f - zv.y) * hv.y + zv.y * q1);
            }
        }
}

// ---------------- launch ----------------
extern "C" void kernel_launch(void* const* d_in, const int* in_sizes, int n_in,
                              void* d_out, int out_size) {
    const float* h   = (const float*)d_in[0];
    const float* x   = (const float*)d_in[1];
    const float* wdz = (const float*)d_in[2];
    const float* bdz = (const float*)d_in[3];
    const float* wpz = (const float*)d_in[4];
    const float* bpz = (const float*)d_in[5];
    const float* wdr = (const float*)d_in[6];
    const float* bdr = (const float*)d_in[7];
    const float* wpr = (const float*)d_in[8];
    const float* bpr = (const float*)d_in[9];
    const float* wdq = (const float*)d_in[10];
    const float* bdq = (const float*)d_in[11];
    const float* wpq = (const float*)d_in[12];
    const float* bpq = (const float*)d_in[13];
    float* out = (float*)d_out;

    cudaFuncSetAttribute(zr_kernel, cudaFuncAttributeMaxDynamicSharedMemorySize, SMEM_ZR);
    cudaFuncSetAttribute(q_kernel,  cudaFuncAttributeMaxDynamicSharedMemorySize, SMEM_Q);

    amax_all_kernel<<<6, 256>>>(wdz, wdr, wdq, wpz, wpr, wpq);       // launch 0
    dim3 gqd((CH * 9 + 255) / 256, 3);
    quant_dw_kernel<<<gqd, 256>>>(wdz, wdr, wdq);                    // launch 1
    dim3 gqp((HID * CH + 255) / 256, 3);
    quant_pw_kernel<<<gqp, 256>>>(wpz, wpr, wpq);                    // launch 2

    zr_kernel<<<512, 512, SMEM_ZR>>>(h, x, bdz, bdr, bpz, bpr);      // launch 3 (ncu capture slot)
    q_kernel <<<512, 512, SMEM_Q >>>(h, x, bdq, bpq, out);           // launch 4
}